// round 1
// baseline (speedup 1.0000x reference)
#include <cuda_runtime.h>

// YOLO loss: pred/target [N_CELLS, 30] f32, choice [N_CELLS] i32 -> 4 f32 scalars.
// Strategy: HBM-bound streaming reduction. Tiles of 128 cells staged via
// coalesced float4 loads into padded (stride-32) shared memory; per-cell
// compute; deterministic two-level reduction (block partials -> final kernel).

#define TILE    128
#define THREADS 128
#define MAX_BLOCKS 8192

// per-block partial sums: [block][6] = {loc, cls, obj, noobj, m_sum, nm_sum}
__device__ float g_part[MAX_BLOCKS * 6];

__global__ __launch_bounds__(THREADS)
void yolo_main(const float* __restrict__ pred,
               const float* __restrict__ target,
               const int*   __restrict__ choice,
               int n_cells)
{
    __shared__ float sp[TILE * 32];   // padded stride 32 -> conflict-free reads
    __shared__ float st[TILE * 32];
    __shared__ float s_red[4 * 6];    // per-warp partials

    const int tid = threadIdx.x;
    const long long base_cell = (long long)blockIdx.x * TILE;
    const int cells_here = (int)min((long long)TILE, (long long)n_cells - base_cell);

    // ---- stage: coalesced float4 global loads, de-interleave into smem ----
    {
        const float4* pg = (const float4*)(pred   + base_cell * 30);
        const float4* tg = (const float4*)(target + base_cell * 30);
        const int nv4 = (cells_here * 30) / 4;          // 960 for full tile
        for (int i = tid; i < nv4; i += THREADS) {
            float4 v = pg[i];
            float4 w = tg[i];
            float pv[4] = {v.x, v.y, v.z, v.w};
            float tv[4] = {w.x, w.y, w.z, w.w};
            int f = i * 4;
            #pragma unroll
            for (int j = 0; j < 4; j++) {
                int idx  = f + j;
                int cell = idx / 30;
                int k    = idx - cell * 30;
                sp[cell * 32 + k] = pv[j];
                st[cell * 32 + k] = tv[j];
            }
        }
        // tail floats if cells_here*30 not divisible by 4 (not hit for full tiles)
        for (int idx = nv4 * 4 + tid; idx < cells_here * 30; idx += THREADS) {
            int cell = idx / 30;
            int k    = idx - cell * 30;
            sp[cell * 32 + k] = pred  [base_cell * 30 + idx];
            st[cell * 32 + k] = target[base_cell * 30 + idx];
        }
    }
    __syncthreads();

    // ---- per-cell compute ----
    float loc = 0.f, clsv = 0.f, objl = 0.f, noobj = 0.f, msum = 0.f, nmsum = 0.f;

    if (tid < cells_here) {
        const float* p = sp + tid * 32;
        const float* t = st + tid * 32;
        const bool c   = choice[base_cell + tid] != 0;
        const int  o   = c ? 0 : 5;

        const float tconf = t[4];
        const bool  ob    = tconf > 0.f;

        if (ob) {
            msum = 1.f;
            // localization
            float dx = p[o + 0] - t[o + 0];
            float dy = p[o + 1] - t[o + 1];
            float dw = p[o + 2] - sqrtf(t[o + 2]);
            float dh = p[o + 3] - sqrtf(t[o + 3]);
            loc = 0.5f * (dx * dx + dy * dy) + 0.5f * (dw * dw + dh * dh);
            // objectness
            float pobj = p[o + 4];
            float tobj = c ? tconf : t[9];
            float d = pobj - tobj;
            objl = d * d;
            // class CE: logp = log_softmax(softmax(logits))
            float mx = -1e30f;
            #pragma unroll
            for (int k = 0; k < 20; k++) mx = fmaxf(mx, p[10 + k]);
            float sm[20];
            float den = 0.f;
            #pragma unroll
            for (int k = 0; k < 20; k++) { sm[k] = expf(p[10 + k] - mx); den += sm[k]; }
            float inv = 1.f / den;
            float m2 = -1e30f;
            #pragma unroll
            for (int k = 0; k < 20; k++) { sm[k] *= inv; m2 = fmaxf(m2, sm[k]); }
            float den2 = 0.f;
            #pragma unroll
            for (int k = 0; k < 20; k++) den2 += expf(sm[k] - m2);
            float lse2 = m2 + logf(den2);
            // argmax of target classes (first max)
            float bm = t[10]; int bi = 0;
            #pragma unroll
            for (int k = 1; k < 20; k++) { float v = t[10 + k]; if (v > bm) { bm = v; bi = k; } }
            clsv = lse2 - sm[bi];
        } else {
            // tconf == 0 exactly here
            nmsum = 1.f;
            float d0 = p[4] - tconf;
            float d1 = p[9] - t[9];
            noobj = d0 * d0 + d1 * d1;
        }
    }

    // ---- deterministic block reduction (warp shuffle tree + cross-warp) ----
    float vals[6] = {loc, clsv, objl, noobj, msum, nmsum};
    #pragma unroll
    for (int v = 0; v < 6; v++) {
        #pragma unroll
        for (int off = 16; off > 0; off >>= 1)
            vals[v] += __shfl_down_sync(0xffffffffu, vals[v], off);
    }
    const int warp = tid >> 5;
    const int lane = tid & 31;
    if (lane == 0) {
        #pragma unroll
        for (int v = 0; v < 6; v++) s_red[warp * 6 + v] = vals[v];
    }
    __syncthreads();
    if (tid == 0) {
        #pragma unroll
        for (int v = 0; v < 6; v++) {
            float s = s_red[v] + s_red[6 + v] + s_red[12 + v] + s_red[18 + v];
            g_part[blockIdx.x * 6 + v] = s;
        }
    }
}

__global__ __launch_bounds__(256)
void yolo_final(float* __restrict__ out, int nblocks)
{
    __shared__ float s[256 * 6];
    const int tid = threadIdx.x;
    float a[6] = {0.f, 0.f, 0.f, 0.f, 0.f, 0.f};
    for (int i = tid; i < nblocks; i += 256) {
        #pragma unroll
        for (int v = 0; v < 6; v++) a[v] += g_part[i * 6 + v];
    }
    #pragma unroll
    for (int v = 0; v < 6; v++) s[tid * 6 + v] = a[v];
    __syncthreads();
    for (int stride = 128; stride > 0; stride >>= 1) {
        if (tid < stride) {
            #pragma unroll
            for (int v = 0; v < 6; v++) s[tid * 6 + v] += s[(tid + stride) * 6 + v];
        }
        __syncthreads();
    }
    if (tid == 0) {
        float loc_sum   = s[0];
        float cls_sum   = s[1];
        float obj_sum   = s[2];
        float noobj_sum = s[3];
        float n_obj = fmaxf(s[4], 1.f);
        float n_no  = fmaxf(s[5], 1.f);
        out[0] = 5.0f * loc_sum;          // loc_loss
        out[1] = cls_sum / n_obj;         // cls_loss
        out[2] = obj_sum;                 // obj_loss
        out[3] = 0.5f * noobj_sum / n_no; // noobj_loss
    }
}

extern "C" void kernel_launch(void* const* d_in, const int* in_sizes, int n_in,
                              void* d_out, int out_size)
{
    const float* pred   = (const float*)d_in[0];
    const float* target = (const float*)d_in[1];
    const int*   choice = (const int*)d_in[2];
    float* out = (float*)d_out;

    const int n_cells = in_sizes[2];
    int nblocks = (n_cells + TILE - 1) / TILE;
    if (nblocks > MAX_BLOCKS) nblocks = MAX_BLOCKS;  // shapes here: 6272 blocks

    yolo_main<<<nblocks, THREADS>>>(pred, target, choice, n_cells);
    yolo_final<<<1, 256>>>(out, nblocks);
}

// round 2
// speedup vs baseline: 1.2323x; 1.2323x over previous
#include <cuda_runtime.h>

// YOLO loss, fused single-kernel version.
// pred/target [N_CELLS, 30] f32, choice [N_CELLS] i32 -> 4 f32 scalars.
// Persistent blocks stream tiles of 128 cells via coalesced float4 -> linear
// smem (STS.128), per-cell compute, per-block accumulation, then a
// deterministic last-block-done global reduction (fixed index order).

#define TILE      128
#define THREADS   128
#define NPART_MAX 2048

__device__ float        g_part[6][NPART_MAX];
__device__ unsigned int g_count = 0;

__device__ __forceinline__ void block_reduce6(float* vals, float* s_red, int tid)
{
    #pragma unroll
    for (int v = 0; v < 6; v++) {
        #pragma unroll
        for (int off = 16; off > 0; off >>= 1)
            vals[v] += __shfl_down_sync(0xffffffffu, vals[v], off);
    }
    const int warp = tid >> 5;
    const int lane = tid & 31;
    if (lane == 0) {
        #pragma unroll
        for (int v = 0; v < 6; v++) s_red[warp * 6 + v] = vals[v];
    }
    __syncthreads();
    if (tid == 0) {
        #pragma unroll
        for (int v = 0; v < 6; v++)
            vals[v] = s_red[v] + s_red[6 + v] + s_red[12 + v] + s_red[18 + v];
    }
}

__global__ __launch_bounds__(THREADS)
void yolo_fused(const float* __restrict__ pred,
                const float* __restrict__ target,
                const int*   __restrict__ choice,
                float*       __restrict__ out,
                int n_cells, int n_tiles)
{
    __shared__ float sp[TILE * 30];      // linear layout, STS.128 staging
    __shared__ float st[TILE * 30];
    __shared__ float s_red[4 * 6];
    __shared__ bool  s_last;

    const int tid = threadIdx.x;
    float acc[6] = {0.f, 0.f, 0.f, 0.f, 0.f, 0.f};

    for (int tile = blockIdx.x; tile < n_tiles; tile += gridDim.x) {
        const long long base_cell = (long long)tile * TILE;
        const int cells_here = (int)min((long long)TILE, (long long)n_cells - base_cell);

        __syncthreads();   // protect smem reuse from previous tile's compute

        // ---- stage: coalesced float4 loads, linear smem stores ----
        {
            const float4* pg = (const float4*)(pred   + base_cell * 30);
            const float4* tg = (const float4*)(target + base_cell * 30);
            float4* sp4 = (float4*)sp;
            float4* st4 = (float4*)st;
            const int nv4 = (cells_here * 30) >> 2;     // 960 for full tile
            #pragma unroll 4
            for (int i = tid; i < nv4; i += THREADS) {
                sp4[i] = pg[i];
                st4[i] = tg[i];
            }
            for (int idx = (nv4 << 2) + tid; idx < cells_here * 30; idx += THREADS) {
                sp[idx] = pred  [base_cell * 30 + idx];
                st[idx] = target[base_cell * 30 + idx];
            }
        }
        __syncthreads();

        // ---- per-cell compute ----
        if (tid < cells_here) {
            const float* p = sp + tid * 30;
            const float* t = st + tid * 30;
            const bool c   = choice[base_cell + tid] != 0;
            const int  o   = c ? 0 : 5;

            const float tconf = t[4];

            if (tconf > 0.f) {
                acc[4] += 1.f;                       // m sum
                // localization
                float dx = p[o + 0] - t[o + 0];
                float dy = p[o + 1] - t[o + 1];
                float dw = p[o + 2] - sqrtf(t[o + 2]);
                float dh = p[o + 3] - sqrtf(t[o + 3]);
                acc[0] += 0.5f * (dx * dx + dy * dy) + 0.5f * (dw * dw + dh * dh);
                // objectness
                float tobj = c ? tconf : t[9];
                float d = p[o + 4] - tobj;
                acc[2] += d * d;
                // class CE: log_softmax(softmax(logits)) gathered at argmax(tcls)
                float mx = -1e30f;
                #pragma unroll
                for (int k = 0; k < 20; k++) mx = fmaxf(mx, p[10 + k]);
                float sm[20];
                float den = 0.f;
                #pragma unroll
                for (int k = 0; k < 20; k++) { sm[k] = expf(p[10 + k] - mx); den += sm[k]; }
                float inv = 1.f / den;
                float m2 = -1e30f;
                #pragma unroll
                for (int k = 0; k < 20; k++) { sm[k] *= inv; m2 = fmaxf(m2, sm[k]); }
                float den2 = 0.f;
                #pragma unroll
                for (int k = 0; k < 20; k++) den2 += expf(sm[k] - m2);
                float lse2 = m2 + logf(den2);
                float bm = t[10]; int bi = 0;
                #pragma unroll
                for (int k = 1; k < 20; k++) { float v = t[10 + k]; if (v > bm) { bm = v; bi = k; } }
                acc[1] += lse2 - sm[bi];
            } else {
                acc[5] += 1.f;                       // nm sum (tconf == 0 here)
                float d0 = p[4] - tconf;
                float d1 = p[9] - t[9];
                acc[3] += d0 * d0 + d1 * d1;
            }
        }
    }

    // ---- per-block reduction ----
    __syncthreads();
    block_reduce6(acc, s_red, tid);

    // ---- publish partials, elect last block ----
    if (tid == 0) {
        #pragma unroll
        for (int v = 0; v < 6; v++) g_part[v][blockIdx.x] = acc[v];
        __threadfence();
        unsigned int ticket = atomicAdd(&g_count, 1u);
        s_last = (ticket == gridDim.x - 1);
    }
    __syncthreads();

    // ---- last block: deterministic final reduction ----
    if (s_last) {
        __threadfence();
        const int npart = gridDim.x;
        float a[6] = {0.f, 0.f, 0.f, 0.f, 0.f, 0.f};
        for (int i = tid; i < npart; i += THREADS) {
            #pragma unroll
            for (int v = 0; v < 6; v++) a[v] += g_part[v][i];
        }
        __syncthreads();
        block_reduce6(a, s_red, tid);
        if (tid == 0) {
            float n_obj = fmaxf(a[4], 1.f);
            float n_no  = fmaxf(a[5], 1.f);
            out[0] = 5.0f * a[0];          // loc_loss
            out[1] = a[1] / n_obj;         // cls_loss
            out[2] = a[2];                 // obj_loss
            out[3] = 0.5f * a[3] / n_no;   // noobj_loss
            g_count = 0;                   // reset for next graph replay
        }
    }
}

extern "C" void kernel_launch(void* const* d_in, const int* in_sizes, int n_in,
                              void* d_out, int out_size)
{
    const float* pred   = (const float*)d_in[0];
    const float* target = (const float*)d_in[1];
    const int*   choice = (const int*)d_in[2];
    float* out = (float*)d_out;

    const int n_cells = in_sizes[2];
    const int n_tiles = (n_cells + TILE - 1) / TILE;

    int grid = n_tiles < 1036 ? n_tiles : 1036;     // 7 CTAs/SM x 148 SMs
    if (grid > NPART_MAX) grid = NPART_MAX;

    yolo_fused<<<grid, THREADS>>>(pred, target, choice, out, n_cells, n_tiles);
}

// round 3
// speedup vs baseline: 1.7123x; 1.3896x over previous
#include <cuda_runtime.h>
#include <cstdint>

// YOLO loss, fused single kernel with cp.async double-buffered streaming.
// pred/target [N_CELLS, 30] f32, choice [N_CELLS] i32 -> 4 f32 scalars.

#define TILE      128
#define THREADS   128
#define NPART_MAX 2048
#define NV4       ((TILE * 30) / 4)      // 960 float4 per array per tile

__device__ float        g_part[6][NPART_MAX];
__device__ unsigned int g_count = 0;

__device__ __forceinline__ void cp_async16(void* smem_dst, const void* gmem_src)
{
    uint32_t s = (uint32_t)__cvta_generic_to_shared(smem_dst);
    asm volatile("cp.async.cg.shared.global [%0], [%1], 16;" :: "r"(s), "l"(gmem_src));
}
__device__ __forceinline__ void cp_commit()
{
    asm volatile("cp.async.commit_group;" ::: "memory");
}
__device__ __forceinline__ void cp_wait1()
{
    asm volatile("cp.async.wait_group 1;" ::: "memory");
}
__device__ __forceinline__ void cp_wait0()
{
    asm volatile("cp.async.wait_group 0;" ::: "memory");
}

struct Stage {
    float sp[TILE * 30];
    float st[TILE * 30];
    int   sc[TILE];
};

__device__ __forceinline__ void prefetch_tile(Stage* stg,
                                              const float* __restrict__ pred,
                                              const float* __restrict__ target,
                                              const int*   __restrict__ choice,
                                              long long base_cell, int tid)
{
    const float4* pg = (const float4*)(pred   + base_cell * 30);
    const float4* tg = (const float4*)(target + base_cell * 30);
    float4* sp4 = (float4*)stg->sp;
    float4* st4 = (float4*)stg->st;
    #pragma unroll
    for (int i = tid; i < NV4; i += THREADS) cp_async16(&sp4[i], &pg[i]);
    #pragma unroll
    for (int i = tid; i < NV4; i += THREADS) cp_async16(&st4[i], &tg[i]);
    // choice: 128 ints = 32 float4
    if (tid < TILE / 4) {
        const float4* cg = (const float4*)(choice + base_cell);
        cp_async16(&((float4*)stg->sc)[tid], &cg[tid]);
    }
}

// per-cell loss terms accumulated into acc[6] = {loc, cls, obj, noobj, m, nm}
__device__ __forceinline__ void cell_compute(const float* __restrict__ p,
                                             const float* __restrict__ t,
                                             bool c, float acc[6])
{
    const int o = c ? 0 : 5;
    const float tconf = t[4];

    if (tconf > 0.f) {
        acc[4] += 1.f;
        float dx = p[o + 0] - t[o + 0];
        float dy = p[o + 1] - t[o + 1];
        float dw = p[o + 2] - sqrtf(t[o + 2]);
        float dh = p[o + 3] - sqrtf(t[o + 3]);
        acc[0] += 0.5f * (dx * dx + dy * dy) + 0.5f * (dw * dw + dh * dh);
        float tobj = c ? tconf : t[9];
        float d = p[o + 4] - tobj;
        acc[2] += d * d;
        // class CE: log_softmax(softmax(logits)) at argmax(target classes)
        float mx = -1e30f;
        #pragma unroll
        for (int k = 0; k < 20; k++) mx = fmaxf(mx, p[10 + k]);
        float sm[20];
        float den = 0.f;
        #pragma unroll
        for (int k = 0; k < 20; k++) { sm[k] = __expf(p[10 + k] - mx); den += sm[k]; }
        float inv = 1.f / den;
        float m2 = -1e30f;
        #pragma unroll
        for (int k = 0; k < 20; k++) { sm[k] *= inv; m2 = fmaxf(m2, sm[k]); }
        float den2 = 0.f;
        #pragma unroll
        for (int k = 0; k < 20; k++) den2 += __expf(sm[k] - m2);
        float lse2 = m2 + __logf(den2);
        float bm = t[10]; int bi = 0;
        #pragma unroll
        for (int k = 1; k < 20; k++) { float v = t[10 + k]; if (v > bm) { bm = v; bi = k; } }
        acc[1] += lse2 - sm[bi];
    } else {
        acc[5] += 1.f;
        float d0 = p[4] - tconf;
        float d1 = p[9] - t[9];
        acc[3] += d0 * d0 + d1 * d1;
    }
}

__device__ __forceinline__ void block_reduce6(float* vals, float* s_red, int tid)
{
    #pragma unroll
    for (int v = 0; v < 6; v++) {
        #pragma unroll
        for (int off = 16; off > 0; off >>= 1)
            vals[v] += __shfl_down_sync(0xffffffffu, vals[v], off);
    }
    const int warp = tid >> 5;
    const int lane = tid & 31;
    if (lane == 0) {
        #pragma unroll
        for (int v = 0; v < 6; v++) s_red[warp * 6 + v] = vals[v];
    }
    __syncthreads();
    if (tid == 0) {
        #pragma unroll
        for (int v = 0; v < 6; v++)
            vals[v] = s_red[v] + s_red[6 + v] + s_red[12 + v] + s_red[18 + v];
    }
}

__global__ __launch_bounds__(THREADS)
void yolo_fused(const float* __restrict__ pred,
                const float* __restrict__ target,
                const int*   __restrict__ choice,
                float*       __restrict__ out,
                int n_cells, int n_tiles)
{
    __shared__ Stage stage[2];
    __shared__ float s_red[4 * 6];
    __shared__ bool  s_last;

    const int tid = threadIdx.x;
    float acc[6] = {0.f, 0.f, 0.f, 0.f, 0.f, 0.f};

    const int first = blockIdx.x;
    const int step  = gridDim.x;

    int cur = 0;
    // prime the pipeline with the first full tile (partial tiles bypass smem)
    if (first < n_tiles) {
        long long base = (long long)first * TILE;
        if (base + TILE <= n_cells)
            prefetch_tile(&stage[0], pred, target, choice, base, tid);
        cp_commit();
    }

    for (int tile = first; tile < n_tiles; tile += step) {
        const long long base_cell = (long long)tile * TILE;
        const int cells_here = (int)min((long long)TILE, (long long)n_cells - base_cell);
        const bool full = (cells_here == TILE);

        const int next = tile + step;
        const bool has_next = next < n_tiles;
        if (has_next) {
            long long nbase = (long long)next * TILE;
            if (nbase + TILE <= n_cells)
                prefetch_tile(&stage[cur ^ 1], pred, target, choice, nbase, tid);
            cp_commit();
            cp_wait1();
        } else {
            cp_wait0();
        }
        __syncthreads();   // current tile resident & all compute on this buffer from
                           // the prior round is done (barrier also orders reuse)

        if (full) {
            const float* p = stage[cur].sp + tid * 30;
            const float* t = stage[cur].st + tid * 30;
            cell_compute(p, t, stage[cur].sc[tid] != 0, acc);
        } else if (tid < cells_here) {
            // rare partial tail tile: read straight from global
            const float* p = pred   + (base_cell + tid) * 30;
            const float* t = target + (base_cell + tid) * 30;
            cell_compute(p, t, choice[base_cell + tid] != 0, acc);
        }
        __syncthreads();   // everyone done reading stage[cur] before next overwrite
        cur ^= 1;
    }

    block_reduce6(acc, s_red, tid);

    if (tid == 0) {
        #pragma unroll
        for (int v = 0; v < 6; v++) g_part[v][blockIdx.x] = acc[v];
        __threadfence();
        unsigned int ticket = atomicAdd(&g_count, 1u);
        s_last = (ticket == gridDim.x - 1);
    }
    __syncthreads();

    if (s_last) {
        __threadfence();
        const int npart = gridDim.x;
        float a[6] = {0.f, 0.f, 0.f, 0.f, 0.f, 0.f};
        for (int i = tid; i < npart; i += THREADS) {
            #pragma unroll
            for (int v = 0; v < 6; v++) a[v] += g_part[v][i];
        }
        __syncthreads();
        block_reduce6(a, s_red, tid);
        if (tid == 0) {
            float n_obj = fmaxf(a[4], 1.f);
            float n_no  = fmaxf(a[5], 1.f);
            out[0] = 5.0f * a[0];
            out[1] = a[1] / n_obj;
            out[2] = a[2];
            out[3] = 0.5f * a[3] / n_no;
            g_count = 0;   // reset for next graph replay
        }
    }
}

extern "C" void kernel_launch(void* const* d_in, const int* in_sizes, int n_in,
                              void* d_out, int out_size)
{
    const float* pred   = (const float*)d_in[0];
    const float* target = (const float*)d_in[1];
    const int*   choice = (const int*)d_in[2];
    float* out = (float*)d_out;

    const int n_cells = in_sizes[2];
    const int n_tiles = (n_cells + TILE - 1) / TILE;

    int grid = 3 * 148;                       // 3 CTAs/SM (62.5 KB smem each)
    if (grid > n_tiles) grid = n_tiles;
    if (grid > NPART_MAX) grid = NPART_MAX;

    yolo_fused<<<grid, THREADS>>>(pred, target, choice, out, n_cells, n_tiles);
}